// round 6
// baseline (speedup 1.0000x reference)
#include <cuda_runtime.h>
#include <cuda_bf16.h>
#include <cstdint>

// ---------------------------------------------------------------- constants
#define EPSV      1e-5f
#define SCALE_QK  0.17677669529663687f   // 1/sqrt(32)

#define BB   64
#define NN   784
#define NQ   196
#define CC   512
#define HH   16
#define OKV  1536
#define OQ   512
#define DH   1024
#define OP   768
#define MKV  (BB*NN)  // 50176
#define MQ   (BB*NQ)  // 12544

// ---------------------------------------------------------------- scratch
__device__ float g_Ykv[(size_t)MKV * OKV];
__device__ float g_Yq [(size_t)MQ  * OQ];
__device__ float g_Yp [(size_t)MQ  * OP];
__device__ float g_ps [64 * OKV];
__device__ float g_pq [64 * OKV];
__device__ float g_sc_kv[OKV], g_sh_kv[OKV];
__device__ float g_sc_q [OQ],  g_sh_q [OQ];
__device__ float g_sc_p [OP],  g_sh_p [OP];

// bf16 split operands
__device__ __nv_bfloat16 g_xh [(size_t)MKV * CC],  g_xl [(size_t)MKV * CC];
__device__ __nv_bfloat16 g_Wkvh[(size_t)OKV * CC], g_Wkvl[(size_t)OKV * CC];
__device__ __nv_bfloat16 g_Wqh [(size_t)OQ  * CC], g_Wql [(size_t)OQ  * CC];
__device__ __nv_bfloat16 g_Wph [(size_t)OP  * DH], g_Wpl [(size_t)OP  * DH];
__device__ __nv_bfloat16 g_Yoh [(size_t)MQ  * DH], g_Yol [(size_t)MQ  * DH];

// ---------------------------------------------------------------- helpers
__device__ __forceinline__ uint32_t smem_u32(const void* p) {
    uint32_t a;
    asm("{ .reg .u64 t; cvta.to.shared.u64 t, %1; cvt.u32.u64 %0, t; }" : "=r"(a) : "l"(p));
    return a;
}
__device__ __forceinline__ void cp_async16(uint32_t dst, const void* src) {
    asm volatile("cp.async.cg.shared.global [%0], [%1], 16;" :: "r"(dst), "l"(src) : "memory");
}
__device__ __forceinline__ void cp_commit() {
    asm volatile("cp.async.commit_group;" ::: "memory");
}
template<int N>
__device__ __forceinline__ void cp_wait() {
    asm volatile("cp.async.wait_group %0;" :: "n"(N) : "memory");
}
__device__ __forceinline__ void mma16816(float* c, uint32_t a0, uint32_t a1,
                                         uint32_t a2, uint32_t a3,
                                         uint32_t b0, uint32_t b1) {
    asm volatile(
        "mma.sync.aligned.m16n8k16.row.col.f32.bf16.bf16.f32 "
        "{%0,%1,%2,%3}, {%4,%5,%6,%7}, {%8,%9}, {%0,%1,%2,%3};"
        : "+f"(c[0]), "+f"(c[1]), "+f"(c[2]), "+f"(c[3])
        : "r"(a0), "r"(a1), "r"(a2), "r"(a3), "r"(b0), "r"(b1));
}
__device__ __forceinline__ void ldsm_x4(uint32_t addr, uint32_t& r0, uint32_t& r1,
                                        uint32_t& r2, uint32_t& r3) {
    asm volatile("ldmatrix.sync.aligned.m8n8.x4.shared.b16 {%0,%1,%2,%3}, [%4];"
        : "=r"(r0), "=r"(r1), "=r"(r2), "=r"(r3) : "r"(addr));
}
__device__ __forceinline__ void ldsm_x2(uint32_t addr, uint32_t& r0, uint32_t& r1) {
    asm volatile("ldmatrix.sync.aligned.m8n8.x2.shared.b16 {%0,%1}, [%2];"
        : "=r"(r0), "=r"(r1) : "r"(addr));
}

// ---------------------------------------------------------------- fp32 -> bf16 hi/lo split
__global__ void __launch_bounds__(256) cvt_split4(
    const float* __restrict__ X, __nv_bfloat16* __restrict__ H,
    __nv_bfloat16* __restrict__ L, size_t n4)
{
    size_t i = (size_t)blockIdx.x * 256 + threadIdx.x;
    if (i >= n4) return;
    float4 v = reinterpret_cast<const float4*>(X)[i];
    __nv_bfloat16 hx = __float2bfloat16(v.x);
    __nv_bfloat16 hy = __float2bfloat16(v.y);
    __nv_bfloat16 hz = __float2bfloat16(v.z);
    __nv_bfloat16 hw = __float2bfloat16(v.w);
    __nv_bfloat16 lx = __float2bfloat16(v.x - __bfloat162float(hx));
    __nv_bfloat16 ly = __float2bfloat16(v.y - __bfloat162float(hy));
    __nv_bfloat16 lz = __float2bfloat16(v.z - __bfloat162float(hz));
    __nv_bfloat16 lw = __float2bfloat16(v.w - __bfloat162float(hw));
    reinterpret_cast<__nv_bfloat162*>(H)[2 * i]     = __halves2bfloat162(hx, hy);
    reinterpret_cast<__nv_bfloat162*>(H)[2 * i + 1] = __halves2bfloat162(hz, hw);
    reinterpret_cast<__nv_bfloat162*>(L)[2 * i]     = __halves2bfloat162(lx, ly);
    reinterpret_cast<__nv_bfloat162*>(L)[2 * i + 1] = __halves2bfloat162(lz, lw);
}

// ---------------------------------------------------------------- mma.sync bf16-split GEMM
// CTA 128x128, 8 warps (4Mx2N), warp tile 32x64, K chunks of 32, cp.async x2,
// ldmatrix fragment loads. smem pitch 80 B/row -> conflict-free LDSM phases.
#define LDA_B    80
#define MAT_B    (128 * LDA_B)          // 10240
#define STAGE_B  (4 * MAT_B)            // 40960
#define GEMM_SMEM (2 * STAGE_B)         // 81920

template<int GATHER>
__device__ __forceinline__ void load_chunk(
    const __nv_bfloat16* __restrict__ Ah_g, const __nv_bfloat16* __restrict__ Al_g,
    const __nv_bfloat16* __restrict__ Bh_g, const __nv_bfloat16* __restrict__ Bl_g,
    uint32_t sbase, int mBase, int nBase, int k0, int K, int tid)
{
    #pragma unroll
    for (int i = 0; i < 8; i++) {
        int u = tid + i * 256;
        int mat = u >> 9;
        int r   = (u >> 2) & 127;
        int seg = u & 3;
        const __nv_bfloat16* src;
        int row;
        if (mat < 2) {
            row = mBase + r;
            if (GATHER) {
                int bb = row / 196;
                int t  = row - bb * 196;
                row = bb * 784 + (t / 14) * 56 + (t % 14) * 2;
            }
            src = (mat == 0) ? Ah_g : Al_g;
        } else {
            row = nBase + r;
            src = (mat == 2) ? Bh_g : Bl_g;
        }
        cp_async16(sbase + mat * MAT_B + r * LDA_B + seg * 16,
                   src + (size_t)row * K + k0 + seg * 8);
    }
}

__device__ __forceinline__ void compute_chunk(
    uint32_t stage, float acc[2][8][4], int wm, int wn, int lane)
{
    const int sub    = lane >> 3;
    const int arow_f = (lane & 7) + ((sub & 1) << 3);
    const int akof   = (sub >> 1) << 3;
    const int brow_f = lane & 7;
    const int bkof   = ((lane >> 3) & 1) << 3;

    #pragma unroll
    for (int ks = 0; ks < 2; ks++) {
        const int kb = ks * 16;
        uint32_t Ahf[2][4], Alf[2][4];
        #pragma unroll
        for (int mt = 0; mt < 2; mt++) {
            uint32_t aaddr = stage + (uint32_t)(wm + mt * 16 + arow_f) * LDA_B
                           + (uint32_t)(kb + akof) * 2;
            ldsm_x4(aaddr,         Ahf[mt][0], Ahf[mt][1], Ahf[mt][2], Ahf[mt][3]);
            ldsm_x4(aaddr + MAT_B, Alf[mt][0], Alf[mt][1], Alf[mt][2], Alf[mt][3]);
        }
        #pragma unroll
        for (int nt = 0; nt < 8; nt++) {
            uint32_t baddr = stage + 2 * MAT_B + (uint32_t)(wn + nt * 8 + brow_f) * LDA_B
                           + (uint32_t)(kb + bkof) * 2;
            uint32_t bh0, bh1, bl0, bl1;
            ldsm_x2(baddr,         bh0, bh1);
            ldsm_x2(baddr + MAT_B, bl0, bl1);
            #pragma unroll
            for (int mt = 0; mt < 2; mt++) {
                mma16816(acc[mt][nt], Ahf[mt][0], Ahf[mt][1], Ahf[mt][2], Ahf[mt][3], bh0, bh1);
                mma16816(acc[mt][nt], Ahf[mt][0], Ahf[mt][1], Ahf[mt][2], Ahf[mt][3], bl0, bl1);
                mma16816(acc[mt][nt], Alf[mt][0], Alf[mt][1], Alf[mt][2], Alf[mt][3], bh0, bh1);
            }
        }
    }
}

template<int GATHER>
__global__ void __launch_bounds__(256) gemm_mma(
    const __nv_bfloat16* __restrict__ Ah_g, const __nv_bfloat16* __restrict__ Al_g,
    const __nv_bfloat16* __restrict__ Bh_g, const __nv_bfloat16* __restrict__ Bl_g,
    float* __restrict__ C, int M, int N, int K)
{
    extern __shared__ char gsm[];
    const int tid = threadIdx.x;
    const int wid = tid >> 5, lane = tid & 31;
    const int mBase = blockIdx.y * 128;
    const int nBase = blockIdx.x * 128;
    const int wm = (wid & 3) * 32;
    const int wn = (wid >> 2) * 64;

    const uint32_t sbase = smem_u32(gsm);

    float acc[2][8][4];
    #pragma unroll
    for (int mt = 0; mt < 2; mt++)
        #pragma unroll
        for (int nt = 0; nt < 8; nt++)
            #pragma unroll
            for (int j = 0; j < 4; j++) acc[mt][nt][j] = 0.f;

    const int nc = K >> 5;

    load_chunk<GATHER>(Ah_g, Al_g, Bh_g, Bl_g, sbase, mBase, nBase, 0, K, tid);
    cp_commit();

    for (int c = 0; c < nc; c++) {
        if (c + 1 < nc) {
            load_chunk<GATHER>(Ah_g, Al_g, Bh_g, Bl_g,
                               sbase + ((c + 1) & 1) * STAGE_B,
                               mBase, nBase, (c + 1) * 32, K, tid);
            cp_commit();
            cp_wait<1>();
        } else {
            cp_wait<0>();
        }
        __syncthreads();
        compute_chunk(sbase + (c & 1) * STAGE_B, acc, wm, wn, lane);
        __syncthreads();
    }

    const uint32_t g  = lane >> 2;
    const uint32_t t4 = lane & 3;
    #pragma unroll
    for (int mt = 0; mt < 2; mt++) {
        #pragma unroll
        for (int nt = 0; nt < 8; nt++) {
            const int col = nBase + wn + nt * 8 + t4 * 2;
            const int r0 = mBase + wm + mt * 16 + g;
            float2 v0 = make_float2(acc[mt][nt][0], acc[mt][nt][1]);
            float2 v1 = make_float2(acc[mt][nt][2], acc[mt][nt][3]);
            *reinterpret_cast<float2*>(C + (size_t)r0 * N + col)       = v0;
            *reinterpret_cast<float2*>(C + (size_t)(r0 + 8) * N + col) = v1;
        }
    }
}

// ---------------------------------------------------------------- column reduce (partial)
__global__ void __launch_bounds__(256) col_partial(
    const float* __restrict__ Y, float* __restrict__ ps, float* __restrict__ pq,
    int M, int Ncols)
{
    const int col = blockIdx.x * 256 + threadIdx.x;
    const int ch  = blockIdx.y;
    const int per = (M + 63) >> 6;
    const int r0 = ch * per;
    int r1 = r0 + per; if (r1 > M) r1 = M;
    float s = 0.f, s2 = 0.f;
    for (int r = r0; r < r1; r++) {
        float v = Y[(size_t)r * Ncols + col];
        s += v;
        s2 = fmaf(v, v, s2);
    }
    ps[ch * Ncols + col] = s;
    pq[ch * Ncols + col] = s2;
}

// ---------------------------------------------------------------- BN finalize
__global__ void __launch_bounds__(256) bn_finalize(
    const float* __restrict__ ps, const float* __restrict__ pq,
    const float* __restrict__ g, const float* __restrict__ b,
    float* __restrict__ scale, float* __restrict__ shift,
    int Ncols, float invM)
{
    const int col = blockIdx.x * 256 + threadIdx.x;
    float s = 0.f, s2 = 0.f;
    for (int c = 0; c < 64; c++) {
        s  += ps[c * Ncols + col];
        s2 += pq[c * Ncols + col];
    }
    float m   = s * invM;
    float var = s2 * invM - m * m;
    float sc  = g[col] * rsqrtf(var + EPSV);
    scale[col] = sc;
    shift[col] = b[col] - m * sc;
}

// ---------------------------------------------------------------- attention (merged per (b,h))
__device__ __forceinline__ float hswish(float x) {
    float t = fminf(fmaxf(x + 3.f, 0.f), 6.f);
    return x * t * (1.f / 6.f);
}

// grid: (H=16, B=64); 768 threads; ~97.5 KB dynamic smem (2 CTAs/SM).
// smem float offsets:
#define O_QST   0        // [32][200]   6400
#define O_KST   6400     // [32][56]    1792
#define O_VS    8192     // [56*64]     3584
#define O_SC    11776    // [196*56]    10976
#define O_BH    22752    // 784
#define O_SCV   23536    // 96
#define O_SHV   23632    // 96
#define O_SCQ   23728    // 32
#define O_SHQ   23760    // 32
#define O_MR    23792    // 196
#define O_LR    23988    // 196
#define O_AR    24184    // 196
#define ATTN_SMEM_F 24380
#define ATTN_SMEM_B (ATTN_SMEM_F * 4)

__global__ void __launch_bounds__(768, 2) attn_flash(
    const float* __restrict__ Ykv, const float* __restrict__ Yq,
    const float* __restrict__ sckv, const float* __restrict__ shkv,
    const float* __restrict__ scq,  const float* __restrict__ shq,
    const float* __restrict__ biases, const int* __restrict__ bidx,
    __nv_bfloat16* __restrict__ Yoh, __nv_bfloat16* __restrict__ Yol)
{
    extern __shared__ float sm[];
    float* qsT = sm + O_QST;
    float* KsT = sm + O_KST;
    float* Vs  = sm + O_VS;
    float* Sc  = sm + O_SC;
    float* bh  = sm + O_BH;
    float* scv = sm + O_SCV; float* shv = sm + O_SHV;
    float* scqh = sm + O_SCQ; float* shqh = sm + O_SHQ;
    float* mrow = sm + O_MR; float* lrow = sm + O_LR; float* arow = sm + O_AR;

    const int tid = threadIdx.x;
    const int h = blockIdx.x, b = blockIdx.y;

    if (tid < 96)       { scv[tid] = sckv[h * 96 + tid]; shv[tid] = shkv[h * 96 + tid]; }
    else if (tid < 128) { int d = tid - 96; scqh[d] = scq[h * 32 + d]; shqh[d] = shq[h * 32 + d]; }
    for (int i = tid; i < 784; i += 768) bh[i] = biases[h * 784 + i];
    if (tid < 196) { mrow[tid] = -1e30f; lrow[tid] = 0.f; arow[tid] = 0.f; }
    __syncthreads();

    // q tile k-major (196 rows, pitch 200)
    for (int e = tid; e < 196 * 32; e += 768) {
        int r = e >> 5, d = e & 31;
        qsT[d * 200 + r] = fmaf(Yq[(size_t)(b * NQ + r) * OQ + h * 32 + d], scqh[d], shqh[d]);
    }

    // thread mappings
    const int ty = tid / 14, tx = tid - (tid / 14) * 14;   // QK: 49x14 tiles of 4x4 (686 threads)
    const bool qact = (tid < 686);
    const int dt = tid & 15, rt = tid >> 4;                // PV: cols dt*4, rows rt+48i
    const int d0 = dt * 4;
    const int sq = tid & 3;                                // softmax quad lane

    int rows[5];
    float4 acc4[5];
    #pragma unroll
    for (int i = 0; i < 5; i++) { rows[i] = rt + 48 * i; acc4[i] = make_float4(0.f, 0.f, 0.f, 0.f); }

    __syncthreads();

    for (int kc = 0; kc < 14; kc++) {
        const int kb = kc * 56;

        // fused K+V chunk load, BN folded
        for (int e = tid; e < 56 * 24; e += 768) {
            int r = e / 24, f = e - r * 24;
            float4 v = *(reinterpret_cast<const float4*>(
                Ykv + (size_t)(b * NN + kb + r) * OKV + h * 96) + f);
            if (f < 8) {
                int d = f * 4;
                KsT[(d + 0) * 56 + r] = fmaf(v.x, scv[d + 0], shv[d + 0]);
                KsT[(d + 1) * 56 + r] = fmaf(v.y, scv[d + 1], shv[d + 1]);
                KsT[(d + 2) * 56 + r] = fmaf(v.z, scv[d + 2], shv[d + 2]);
                KsT[(d + 3) * 56 + r] = fmaf(v.w, scv[d + 3], shv[d + 3]);
            } else {
                int d = (f - 8) * 4;
                float4 o;
                o.x = fmaf(v.x, scv[32 + d + 0], shv[32 + d + 0]);
                o.y = fmaf(v.y, scv[32 + d + 1], shv[32 + d + 1]);
                o.z = fmaf(v.z, scv[32 + d + 2], shv[32 + d + 2]);
                o.w = fmaf(v.w, scv[32 + d + 3], shv[32 + d + 3]);
                *reinterpret_cast<float4*>(&Vs[r * 64 + d]) = o;
            }
        }
        __syncthreads();

        // S chunk: 196x56, 4x4 thread tiles
        if (qact) {
            float acc[4][4];
            #pragma unroll
            for (int i = 0; i < 4; i++)
                #pragma unroll
                for (int j = 0; j < 4; j++) acc[i][j] = 0.f;
            #pragma unroll
            for (int k = 0; k < 32; k++) {
                float4 a = *reinterpret_cast<const float4*>(&qsT[k * 200 + ty * 4]);
                float4 bq = *reinterpret_cast<const float4*>(&KsT[k * 56 + tx * 4]);
                float av[4] = {a.x, a.y, a.z, a.w};
                float bv[4] = {bq.x, bq.y, bq.z, bq.w};
                #pragma unroll
                for (int i = 0; i < 4; i++)
                    #pragma unroll
                    for (int j = 0; j < 4; j++)
                        acc[i][j] = fmaf(av[i], bv[j], acc[i][j]);
            }
            #pragma unroll
            for (int i = 0; i < 4; i++) {
                int r = ty * 4 + i;
                int4 id4 = *reinterpret_cast<const int4*>(
                    &bidx[(size_t)r * NN + kb + tx * 4]);
                float* sp = &Sc[r * 56 + tx * 4];
                sp[0] = fmaf(acc[i][0], SCALE_QK, bh[id4.x]);
                sp[1] = fmaf(acc[i][1], SCALE_QK, bh[id4.y]);
                sp[2] = fmaf(acc[i][2], SCALE_QK, bh[id4.z]);
                sp[3] = fmaf(acc[i][3], SCALE_QK, bh[id4.w]);
            }
        }
        __syncthreads();

        // online softmax: quad per row, uniform 2 iterations (shfl-safe)
        #pragma unroll
        for (int it = 0; it < 2; it++) {
            int r = (tid >> 2) + 192 * it;
            bool act = (r < 196);
            int rr = act ? r : 0;
            float cm = -1e30f;
            #pragma unroll
            for (int j = 0; j < 14; j++)
                cm = fmaxf(cm, Sc[rr * 56 + sq + 4 * j]);
            cm = fmaxf(cm, __shfl_xor_sync(0xffffffffu, cm, 1));
            cm = fmaxf(cm, __shfl_xor_sync(0xffffffffu, cm, 2));
            float mo = mrow[rr];
            float mn = fmaxf(mo, cm);
            float cs = 0.f;
            #pragma unroll
            for (int j = 0; j < 14; j++) {
                float p = __expf(Sc[rr * 56 + sq + 4 * j] - mn);
                if (act) Sc[rr * 56 + sq + 4 * j] = p;
                cs += p;
            }
            cs += __shfl_xor_sync(0xffffffffu, cs, 1);
            cs += __shfl_xor_sync(0xffffffffu, cs, 2);
            if (act && sq == 0) {
                float a = __expf(mo - mn);
                arow[rr] = a;
                lrow[rr] = lrow[rr] * a + cs;
                mrow[rr] = mn;
            }
        }
        __syncthreads();

        // PV accumulate with rescale
        float al[5];
        #pragma unroll
        for (int i = 0; i < 5; i++) al[i] = (rows[i] < 196) ? arow[rows[i]] : 0.f;
        #pragma unroll
        for (int i = 0; i < 5; i++) {
            acc4[i].x *= al[i]; acc4[i].y *= al[i];
            acc4[i].z *= al[i]; acc4[i].w *= al[i];
        }
        for (int cb = 0; cb < 56; cb += 4) {
            float4 sv[5];
            #pragma unroll
            for (int i = 0; i < 5; i++)
                sv[i] = (rows[i] < 196)
                      ? *reinterpret_cast<const float4*>(&Sc[rows[i] * 56 + cb])
                      : make_float4(0.f, 0.f, 0.f, 0.f);
            #pragma unroll
            for (int cc = 0; cc < 4; cc++) {
                float4 vv = *reinterpret_cast<const float4*>(&Vs[(cb + cc) * 64 + d0]);
                #pragma unroll
                for (int i = 0; i < 5; i++) {
                    float s = (cc == 0) ? sv[i].x : (cc == 1) ? sv[i].y
                            : (cc == 2) ? sv[i].z : sv[i].w;
                    acc4[i].x = fmaf(s, vv.x, acc4[i].x);
                    acc4[i].y = fmaf(s, vv.y, acc4[i].y);
                    acc4[i].z = fmaf(s, vv.z, acc4[i].z);
                    acc4[i].w = fmaf(s, vv.w, acc4[i].w);
                }
            }
        }
        __syncthreads();
    }

    #pragma unroll
    for (int i = 0; i < 5; i++) {
        int r = rows[i];
        if (r >= 196) continue;
        float inv = 1.0f / lrow[r];
        float o[4] = {hswish(acc4[i].x * inv), hswish(acc4[i].y * inv),
                      hswish(acc4[i].z * inv), hswish(acc4[i].w * inv)};
        __nv_bfloat16 hh[4], ll[4];
        #pragma unroll
        for (int j = 0; j < 4; j++) {
            hh[j] = __float2bfloat16(o[j]);
            ll[j] = __float2bfloat16(o[j] - __bfloat162float(hh[j]));
        }
        size_t base = (size_t)(b * NQ + r) * DH + h * 64 + d0;
        reinterpret_cast<__nv_bfloat162*>(Yoh + base)[0] = __halves2bfloat162(hh[0], hh[1]);
        reinterpret_cast<__nv_bfloat162*>(Yoh + base)[1] = __halves2bfloat162(hh[2], hh[3]);
        reinterpret_cast<__nv_bfloat162*>(Yol + base)[0] = __halves2bfloat162(ll[0], ll[1]);
        reinterpret_cast<__nv_bfloat162*>(Yol + base)[1] = __halves2bfloat162(ll[2], ll[3]);
    }
}

// ---------------------------------------------------------------- final BN apply
__global__ void __launch_bounds__(256) bn_apply(
    const float* __restrict__ Y, const float* __restrict__ scale,
    const float* __restrict__ shift, float* __restrict__ out, int Ncols)
{
    const int idx = blockIdx.x * 256 + threadIdx.x;
    const int c = idx % Ncols;
    out[idx] = fmaf(Y[idx], scale[c], shift[c]);
}

// ---------------------------------------------------------------- launch
extern "C" void kernel_launch(void* const* d_in, const int* in_sizes, int n_in,
                              void* d_out, int out_size)
{
    const float* x    = (const float*)d_in[0];
    const float* W_kv = (const float*)d_in[1];
    const float* gkv  = (const float*)d_in[2];
    const float* bkv  = (const float*)d_in[3];
    const float* W_q  = (const float*)d_in[4];
    const float* gq   = (const float*)d_in[5];
    const float* bq   = (const float*)d_in[6];
    const float* W_p  = (const float*)d_in[7];
    const float* gp   = (const float*)d_in[8];
    const float* bp   = (const float*)d_in[9];
    const float* ab   = (const float*)d_in[10];
    const int*   bidx = (const int*)d_in[11];
    float* out = (float*)d_out;

    float *Ykv, *Yq, *Yp, *ps, *pq;
    float *sckv, *shkv, *scq, *shq, *scp, *shp;
    __nv_bfloat16 *xh, *xl, *Wkvh, *Wkvl, *Wqh, *Wql, *Wph, *Wpl, *Yoh, *Yol;
    cudaGetSymbolAddress((void**)&Ykv, g_Ykv);
    cudaGetSymbolAddress((void**)&Yq,  g_Yq);
    cudaGetSymbolAddress((void**)&Yp,  g_Yp);
    cudaGetSymbolAddress((void**)&ps,  g_ps);
    cudaGetSymbolAddress((void**)&pq,  g_pq);
    cudaGetSymbolAddress((void**)&sckv, g_sc_kv);
    cudaGetSymbolAddress((void**)&shkv, g_sh_kv);
    cudaGetSymbolAddress((void**)&scq,  g_sc_q);
    cudaGetSymbolAddress((void**)&shq,  g_sh_q);
    cudaGetSymbolAddress((void**)&scp,  g_sc_p);
    cudaGetSymbolAddress((void**)&shp,  g_sh_p);
    cudaGetSymbolAddress((void**)&xh,   g_xh);
    cudaGetSymbolAddress((void**)&xl,   g_xl);
    cudaGetSymbolAddress((void**)&Wkvh, g_Wkvh);
    cudaGetSymbolAddress((void**)&Wkvl, g_Wkvl);
    cudaGetSymbolAddress((void**)&Wqh,  g_Wqh);
    cudaGetSymbolAddress((void**)&Wql,  g_Wql);
    cudaGetSymbolAddress((void**)&Wph,  g_Wph);
    cudaGetSymbolAddress((void**)&Wpl,  g_Wpl);
    cudaGetSymbolAddress((void**)&Yoh,  g_Yoh);
    cudaGetSymbolAddress((void**)&Yol,  g_Yol);

    cudaFuncSetAttribute(gemm_mma<0>, cudaFuncAttributeMaxDynamicSharedMemorySize, GEMM_SMEM);
    cudaFuncSetAttribute(gemm_mma<1>, cudaFuncAttributeMaxDynamicSharedMemorySize, GEMM_SMEM);
    cudaFuncSetAttribute(attn_flash, cudaFuncAttributeMaxDynamicSharedMemorySize, ATTN_SMEM_B);

    // 0) bf16 hi/lo splits
    cvt_split4<<<(unsigned)(((size_t)MKV * CC / 4 + 255) / 256), 256>>>(x, xh, xl, (size_t)MKV * CC / 4);
    cvt_split4<<<(unsigned)(((size_t)OKV * CC / 4 + 255) / 256), 256>>>(W_kv, Wkvh, Wkvl, (size_t)OKV * CC / 4);
    cvt_split4<<<(unsigned)(((size_t)OQ  * CC / 4 + 255) / 256), 256>>>(W_q, Wqh, Wql, (size_t)OQ * CC / 4);
    cvt_split4<<<(unsigned)(((size_t)OP  * DH / 4 + 255) / 256), 256>>>(W_p, Wph, Wpl, (size_t)OP * DH / 4);

    // 1) kv = x @ W_kv^T
    gemm_mma<0><<<dim3(OKV / 128, MKV / 128), 256, GEMM_SMEM>>>(xh, xl, Wkvh, Wkvl, Ykv, MKV, OKV, CC);
    col_partial<<<dim3(OKV / 256, 64), 256>>>(Ykv, ps, pq, MKV, OKV);
    bn_finalize<<<OKV / 256, 256>>>(ps, pq, gkv, bkv, sckv, shkv, OKV, 1.f / MKV);

    // 2) q = xq @ W_q^T (gathered rows)
    gemm_mma<1><<<dim3(OQ / 128, MQ / 128), 256, GEMM_SMEM>>>(xh, xl, Wqh, Wql, Yq, MQ, OQ, CC);
    col_partial<<<dim3(OQ / 256, 64), 256>>>(Yq, ps, pq, MQ, OQ);
    bn_finalize<<<OQ / 256, 256>>>(ps, pq, gq, bq, scq, shq, OQ, 1.f / MQ);

    // 3) attention + hard-swish (merged per (b,h); writes bf16 hi/lo)
    attn_flash<<<dim3(HH, BB), 768, ATTN_SMEM_B>>>(
        Ykv, Yq, sckv, shkv, scq, shq, ab, bidx, Yoh, Yol);

    // 4) proj
    gemm_mma<0><<<dim3(OP / 128, MQ / 128), 256, GEMM_SMEM>>>(Yoh, Yol, Wph, Wpl, Yp, MQ, OP, DH);
    col_partial<<<dim3(OP / 256, 64), 256>>>(Yp, ps, pq, MQ, OP);
    bn_finalize<<<OP / 256, 256>>>(ps, pq, gp, bp, scp, shp, OP, 1.f / MQ);
    bn_apply<<<(MQ * OP) / 256, 256>>>(Yp, scp, shp, out, OP);
}

// round 7
// speedup vs baseline: 1.2549x; 1.2549x over previous
#include <cuda_runtime.h>
#include <cuda_bf16.h>
#include <cstdint>

// ---------------------------------------------------------------- constants
#define EPSV      1e-5f
#define SCALE_QK  0.17677669529663687f   // 1/sqrt(32)

#define BB   64
#define NN   784
#define NQ   196
#define CC   512
#define HH   16
#define OKV  1536
#define OQ   512
#define DH   1024
#define OP   768
#define MKV  (BB*NN)  // 50176
#define MQ   (BB*NQ)  // 12544

// ---------------------------------------------------------------- scratch
__device__ float g_Ykv[(size_t)MKV * OKV];
__device__ float g_Yq [(size_t)MQ  * OQ];
__device__ float g_Yp [(size_t)MQ  * OP];
__device__ float g_ps [64 * OKV];
__device__ float g_pq [64 * OKV];
__device__ float g_sc_kv[OKV], g_sh_kv[OKV];
__device__ float g_sc_q [OQ],  g_sh_q [OQ];
__device__ float g_sc_p [OP],  g_sh_p [OP];

// bf16 split operands
__device__ __nv_bfloat16 g_xh [(size_t)MKV * CC],  g_xl [(size_t)MKV * CC];
__device__ __nv_bfloat16 g_Wkvh[(size_t)OKV * CC], g_Wkvl[(size_t)OKV * CC];
__device__ __nv_bfloat16 g_Wqh [(size_t)OQ  * CC], g_Wql [(size_t)OQ  * CC];
__device__ __nv_bfloat16 g_Wph [(size_t)OP  * DH], g_Wpl [(size_t)OP  * DH];
__device__ __nv_bfloat16 g_Yoh [(size_t)MQ  * DH], g_Yol [(size_t)MQ  * DH];

// ---------------------------------------------------------------- helpers
__device__ __forceinline__ uint32_t smem_u32(const void* p) {
    uint32_t a;
    asm("{ .reg .u64 t; cvta.to.shared.u64 t, %1; cvt.u32.u64 %0, t; }" : "=r"(a) : "l"(p));
    return a;
}
__device__ __forceinline__ void cp_async16(uint32_t dst, const void* src) {
    asm volatile("cp.async.cg.shared.global [%0], [%1], 16;" :: "r"(dst), "l"(src) : "memory");
}
__device__ __forceinline__ void cp_commit() {
    asm volatile("cp.async.commit_group;" ::: "memory");
}
template<int N>
__device__ __forceinline__ void cp_wait() {
    asm volatile("cp.async.wait_group %0;" :: "n"(N) : "memory");
}
__device__ __forceinline__ void mma16816(float* c, uint32_t a0, uint32_t a1,
                                         uint32_t a2, uint32_t a3,
                                         uint32_t b0, uint32_t b1) {
    asm volatile(
        "mma.sync.aligned.m16n8k16.row.col.f32.bf16.bf16.f32 "
        "{%0,%1,%2,%3}, {%4,%5,%6,%7}, {%8,%9}, {%0,%1,%2,%3};"
        : "+f"(c[0]), "+f"(c[1]), "+f"(c[2]), "+f"(c[3])
        : "r"(a0), "r"(a1), "r"(a2), "r"(a3), "r"(b0), "r"(b1));
}
__device__ __forceinline__ void ldsm_x4(uint32_t addr, uint32_t& r0, uint32_t& r1,
                                        uint32_t& r2, uint32_t& r3) {
    asm volatile("ldmatrix.sync.aligned.m8n8.x4.shared.b16 {%0,%1,%2,%3}, [%4];"
        : "=r"(r0), "=r"(r1), "=r"(r2), "=r"(r3) : "r"(addr));
}
__device__ __forceinline__ void ldsm_x2(uint32_t addr, uint32_t& r0, uint32_t& r1) {
    asm volatile("ldmatrix.sync.aligned.m8n8.x2.shared.b16 {%0,%1}, [%2];"
        : "=r"(r0), "=r"(r1) : "r"(addr));
}

// ---------------------------------------------------------------- fp32 -> bf16 hi/lo split
__global__ void __launch_bounds__(256) cvt_split4(
    const float* __restrict__ X, __nv_bfloat16* __restrict__ H,
    __nv_bfloat16* __restrict__ L, size_t n4)
{
    size_t i = (size_t)blockIdx.x * 256 + threadIdx.x;
    if (i >= n4) return;
    float4 v = reinterpret_cast<const float4*>(X)[i];
    __nv_bfloat16 hx = __float2bfloat16(v.x);
    __nv_bfloat16 hy = __float2bfloat16(v.y);
    __nv_bfloat16 hz = __float2bfloat16(v.z);
    __nv_bfloat16 hw = __float2bfloat16(v.w);
    __nv_bfloat16 lx = __float2bfloat16(v.x - __bfloat162float(hx));
    __nv_bfloat16 ly = __float2bfloat16(v.y - __bfloat162float(hy));
    __nv_bfloat16 lz = __float2bfloat16(v.z - __bfloat162float(hz));
    __nv_bfloat16 lw = __float2bfloat16(v.w - __bfloat162float(hw));
    reinterpret_cast<__nv_bfloat162*>(H)[2 * i]     = __halves2bfloat162(hx, hy);
    reinterpret_cast<__nv_bfloat162*>(H)[2 * i + 1] = __halves2bfloat162(hz, hw);
    reinterpret_cast<__nv_bfloat162*>(L)[2 * i]     = __halves2bfloat162(lx, ly);
    reinterpret_cast<__nv_bfloat162*>(L)[2 * i + 1] = __halves2bfloat162(lz, lw);
}

// ---------------------------------------------------------------- mma.sync bf16-split GEMM
// CTA 128x128, 8 warps (4Mx2N), warp tile 32x64, K chunks of 32, cp.async x2,
// ldmatrix fragment loads. smem pitch 80 B/row -> conflict-free LDSM phases.
#define LDA_B    80
#define MAT_B    (128 * LDA_B)          // 10240
#define STAGE_B  (4 * MAT_B)            // 40960
#define GEMM_SMEM (2 * STAGE_B)         // 81920

template<int GATHER>
__device__ __forceinline__ void load_chunk(
    const __nv_bfloat16* __restrict__ Ah_g, const __nv_bfloat16* __restrict__ Al_g,
    const __nv_bfloat16* __restrict__ Bh_g, const __nv_bfloat16* __restrict__ Bl_g,
    uint32_t sbase, int mBase, int nBase, int k0, int K, int tid)
{
    #pragma unroll
    for (int i = 0; i < 8; i++) {
        int u = tid + i * 256;
        int mat = u >> 9;
        int r   = (u >> 2) & 127;
        int seg = u & 3;
        const __nv_bfloat16* src;
        int row;
        if (mat < 2) {
            row = mBase + r;
            if (GATHER) {
                int bb = row / 196;
                int t  = row - bb * 196;
                row = bb * 784 + (t / 14) * 56 + (t % 14) * 2;
            }
            src = (mat == 0) ? Ah_g : Al_g;
        } else {
            row = nBase + r;
            src = (mat == 2) ? Bh_g : Bl_g;
        }
        cp_async16(sbase + mat * MAT_B + r * LDA_B + seg * 16,
                   src + (size_t)row * K + k0 + seg * 8);
    }
}

__device__ __forceinline__ void compute_chunk(
    uint32_t stage, float acc[2][8][4], int wm, int wn, int lane)
{
    const int sub    = lane >> 3;
    const int arow_f = (lane & 7) + ((sub & 1) << 3);
    const int akof   = (sub >> 1) << 3;
    const int brow_f = lane & 7;
    const int bkof   = ((lane >> 3) & 1) << 3;

    #pragma unroll
    for (int ks = 0; ks < 2; ks++) {
        const int kb = ks * 16;
        uint32_t Ahf[2][4], Alf[2][4];
        #pragma unroll
        for (int mt = 0; mt < 2; mt++) {
            uint32_t aaddr = stage + (uint32_t)(wm + mt * 16 + arow_f) * LDA_B
                           + (uint32_t)(kb + akof) * 2;
            ldsm_x4(aaddr,         Ahf[mt][0], Ahf[mt][1], Ahf[mt][2], Ahf[mt][3]);
            ldsm_x4(aaddr + MAT_B, Alf[mt][0], Alf[mt][1], Alf[mt][2], Alf[mt][3]);
        }
        #pragma unroll
        for (int nt = 0; nt < 8; nt++) {
            uint32_t baddr = stage + 2 * MAT_B + (uint32_t)(wn + nt * 8 + brow_f) * LDA_B
                           + (uint32_t)(kb + bkof) * 2;
            uint32_t bh0, bh1, bl0, bl1;
            ldsm_x2(baddr,         bh0, bh1);
            ldsm_x2(baddr + MAT_B, bl0, bl1);
            #pragma unroll
            for (int mt = 0; mt < 2; mt++) {
                mma16816(acc[mt][nt], Ahf[mt][0], Ahf[mt][1], Ahf[mt][2], Ahf[mt][3], bh0, bh1);
                mma16816(acc[mt][nt], Ahf[mt][0], Ahf[mt][1], Ahf[mt][2], Ahf[mt][3], bl0, bl1);
                mma16816(acc[mt][nt], Alf[mt][0], Alf[mt][1], Alf[mt][2], Alf[mt][3], bh0, bh1);
            }
        }
    }
}

template<int GATHER>
__global__ void __launch_bounds__(256) gemm_mma(
    const __nv_bfloat16* __restrict__ Ah_g, const __nv_bfloat16* __restrict__ Al_g,
    const __nv_bfloat16* __restrict__ Bh_g, const __nv_bfloat16* __restrict__ Bl_g,
    float* __restrict__ C, int M, int N, int K)
{
    extern __shared__ char gsm[];
    const int tid = threadIdx.x;
    const int wid = tid >> 5, lane = tid & 31;
    const int mBase = blockIdx.y * 128;
    const int nBase = blockIdx.x * 128;
    const int wm = (wid & 3) * 32;
    const int wn = (wid >> 2) * 64;

    const uint32_t sbase = smem_u32(gsm);

    float acc[2][8][4];
    #pragma unroll
    for (int mt = 0; mt < 2; mt++)
        #pragma unroll
        for (int nt = 0; nt < 8; nt++)
            #pragma unroll
            for (int j = 0; j < 4; j++) acc[mt][nt][j] = 0.f;

    const int nc = K >> 5;

    load_chunk<GATHER>(Ah_g, Al_g, Bh_g, Bl_g, sbase, mBase, nBase, 0, K, tid);
    cp_commit();

    for (int c = 0; c < nc; c++) {
        if (c + 1 < nc) {
            load_chunk<GATHER>(Ah_g, Al_g, Bh_g, Bl_g,
                               sbase + ((c + 1) & 1) * STAGE_B,
                               mBase, nBase, (c + 1) * 32, K, tid);
            cp_commit();
            cp_wait<1>();
        } else {
            cp_wait<0>();
        }
        __syncthreads();
        compute_chunk(sbase + (c & 1) * STAGE_B, acc, wm, wn, lane);
        __syncthreads();
    }

    const uint32_t g  = lane >> 2;
    const uint32_t t4 = lane & 3;
    #pragma unroll
    for (int mt = 0; mt < 2; mt++) {
        #pragma unroll
        for (int nt = 0; nt < 8; nt++) {
            const int col = nBase + wn + nt * 8 + t4 * 2;
            const int r0 = mBase + wm + mt * 16 + g;
            float2 v0 = make_float2(acc[mt][nt][0], acc[mt][nt][1]);
            float2 v1 = make_float2(acc[mt][nt][2], acc[mt][nt][3]);
            *reinterpret_cast<float2*>(C + (size_t)r0 * N + col)       = v0;
            *reinterpret_cast<float2*>(C + (size_t)(r0 + 8) * N + col) = v1;
        }
    }
}

// ---------------------------------------------------------------- column reduce (partial)
__global__ void __launch_bounds__(256) col_partial(
    const float* __restrict__ Y, float* __restrict__ ps, float* __restrict__ pq,
    int M, int Ncols)
{
    const int col = blockIdx.x * 256 + threadIdx.x;
    const int ch  = blockIdx.y;
    const int per = (M + 63) >> 6;
    const int r0 = ch * per;
    int r1 = r0 + per; if (r1 > M) r1 = M;
    float s = 0.f, s2 = 0.f;
    for (int r = r0; r < r1; r++) {
        float v = Y[(size_t)r * Ncols + col];
        s += v;
        s2 = fmaf(v, v, s2);
    }
    ps[ch * Ncols + col] = s;
    pq[ch * Ncols + col] = s2;
}

// ---------------------------------------------------------------- BN finalize
__global__ void __launch_bounds__(256) bn_finalize(
    const float* __restrict__ ps, const float* __restrict__ pq,
    const float* __restrict__ g, const float* __restrict__ b,
    float* __restrict__ scale, float* __restrict__ shift,
    int Ncols, float invM)
{
    const int col = blockIdx.x * 256 + threadIdx.x;
    float s = 0.f, s2 = 0.f;
    for (int c = 0; c < 64; c++) {
        s  += ps[c * Ncols + col];
        s2 += pq[c * Ncols + col];
    }
    float m   = s * invM;
    float var = s2 * invM - m * m;
    float sc  = g[col] * rsqrtf(var + EPSV);
    scale[col] = sc;
    shift[col] = b[col] - m * sc;
}

// ---------------------------------------------------------------- attention (flash-style, round-5)
__device__ __forceinline__ float hswish(float x) {
    float t = fminf(fmaxf(x + 3.f, 0.f), 6.f);
    return x * t * (1.f / 6.f);
}

__global__ void __launch_bounds__(256) attn_flash(
    const float* __restrict__ Ykv, const float* __restrict__ Yq,
    const float* __restrict__ sckv, const float* __restrict__ shkv,
    const float* __restrict__ scq,  const float* __restrict__ shq,
    const float* __restrict__ biases, const int* __restrict__ bidx,
    __nv_bfloat16* __restrict__ Yoh, __nv_bfloat16* __restrict__ Yol)
{
    __shared__ float qsT[32][64];
    __shared__ float KsT[32][56];
    __shared__ float Vs[56 * 64];
    __shared__ float Sc[49 * 56];
    __shared__ float bh[784];
    __shared__ float scv[96], shv[96], scqh[32], shqh[32];
    __shared__ float mrow[49], lrow[49], arow[49];

    const int tid = threadIdx.x;
    const int qg = blockIdx.x, h = blockIdx.y, b = blockIdx.z;

    if (tid < 96)       { scv[tid] = sckv[h * 96 + tid]; shv[tid] = shkv[h * 96 + tid]; }
    else if (tid < 128) { int d = tid - 96; scqh[d] = scq[h * 32 + d]; shqh[d] = shq[h * 32 + d]; }
    for (int i = tid; i < 784; i += 256) bh[i] = biases[h * 784 + i];
    if (tid < 49) { mrow[tid] = -1e30f; lrow[tid] = 0.f; arow[tid] = 0.f; }
    __syncthreads();

    for (int e = tid; e < 64 * 32; e += 256) {
        int r = e >> 5, d = e & 31;
        float v = 0.f;
        if (r < 49) {
            int qi = qg * 49 + r;
            v = fmaf(Yq[(size_t)(b * NQ + qi) * OQ + h * 32 + d], scqh[d], shqh[d]);
        }
        qsT[d][r] = v;
    }

    const int ty = tid >> 4, tx = tid & 15;
    const int dt = tid & 15, rt = tid >> 4;
    const int d0 = dt * 4;
    const int sr = (tid < 196) ? (tid >> 2) : 48;
    const int sq = tid & 3;
    const bool sact = (tid < 196);

    int rows[4];
    float4 acc4[4];
    #pragma unroll
    for (int i = 0; i < 4; i++) { rows[i] = rt + 16 * i; acc4[i] = make_float4(0.f, 0.f, 0.f, 0.f); }

    __syncthreads();

    for (int kc = 0; kc < 14; kc++) {
        const int kb = kc * 56;

        for (int e = tid; e < 56 * 24; e += 256) {
            int r = e / 24, f = e - r * 24;
            float4 v = *(reinterpret_cast<const float4*>(
                Ykv + (size_t)(b * NN + kb + r) * OKV + h * 96) + f);
            if (f < 8) {
                int d = f * 4;
                KsT[d + 0][r] = fmaf(v.x, scv[d + 0], shv[d + 0]);
                KsT[d + 1][r] = fmaf(v.y, scv[d + 1], shv[d + 1]);
                KsT[d + 2][r] = fmaf(v.z, scv[d + 2], shv[d + 2]);
                KsT[d + 3][r] = fmaf(v.w, scv[d + 3], shv[d + 3]);
            } else {
                int d = (f - 8) * 4;
                float4 o;
                o.x = fmaf(v.x, scv[32 + d + 0], shv[32 + d + 0]);
                o.y = fmaf(v.y, scv[32 + d + 1], shv[32 + d + 1]);
                o.z = fmaf(v.z, scv[32 + d + 2], shv[32 + d + 2]);
                o.w = fmaf(v.w, scv[32 + d + 3], shv[32 + d + 3]);
                *reinterpret_cast<float4*>(&Vs[r * 64 + d]) = o;
            }
        }
        __syncthreads();

        if (tx < 14) {
            float acc[4][4];
            #pragma unroll
            for (int i = 0; i < 4; i++)
                #pragma unroll
                for (int j = 0; j < 4; j++) acc[i][j] = 0.f;
            #pragma unroll
            for (int k = 0; k < 32; k++) {
                float4 a = *reinterpret_cast<const float4*>(&qsT[k][ty * 4]);
                float4 bq = *reinterpret_cast<const float4*>(&KsT[k][tx * 4]);
                float av[4] = {a.x, a.y, a.z, a.w};
                float bv[4] = {bq.x, bq.y, bq.z, bq.w};
                #pragma unroll
                for (int i = 0; i < 4; i++)
                    #pragma unroll
                    for (int j = 0; j < 4; j++)
                        acc[i][j] = fmaf(av[i], bv[j], acc[i][j]);
            }
            #pragma unroll
            for (int i = 0; i < 4; i++) {
                int r = ty * 4 + i;
                if (r < 49) {
                    int4 id4 = *reinterpret_cast<const int4*>(
                        &bidx[(size_t)(qg * 49 + r) * NN + kb + tx * 4]);
                    float* sp = &Sc[r * 56 + tx * 4];
                    sp[0] = fmaf(acc[i][0], SCALE_QK, bh[id4.x]);
                    sp[1] = fmaf(acc[i][1], SCALE_QK, bh[id4.y]);
                    sp[2] = fmaf(acc[i][2], SCALE_QK, bh[id4.z]);
                    sp[3] = fmaf(acc[i][3], SCALE_QK, bh[id4.w]);
                }
            }
        }
        __syncthreads();

        {
            float xv[14];
            float cm = -1e30f;
            #pragma unroll
            for (int j = 0; j < 14; j++) {
                xv[j] = Sc[sr * 56 + sq + 4 * j];
                cm = fmaxf(cm, xv[j]);
            }
            cm = fmaxf(cm, __shfl_xor_sync(0xffffffffu, cm, 1));
            cm = fmaxf(cm, __shfl_xor_sync(0xffffffffu, cm, 2));
            float mo = mrow[sr];
            float mn = fmaxf(mo, cm);
            float cs = 0.f;
            #pragma unroll
            for (int j = 0; j < 14; j++) {
                float p = __expf(xv[j] - mn);
                xv[j] = p;
                cs += p;
            }
            cs += __shfl_xor_sync(0xffffffffu, cs, 1);
            cs += __shfl_xor_sync(0xffffffffu, cs, 2);
            if (sact) {
                #pragma unroll
                for (int j = 0; j < 14; j++) Sc[sr * 56 + sq + 4 * j] = xv[j];
                if (sq == 0) {
                    float a = __expf(mo - mn);
                    arow[sr] = a;
                    lrow[sr] = lrow[sr] * a + cs;
                    mrow[sr] = mn;
                }
            }
        }
        __syncthreads();

        float al[4];
        #pragma unroll
        for (int i = 0; i < 4; i++) al[i] = (rows[i] < 49) ? arow[rows[i]] : 0.f;
        #pragma unroll
        for (int i = 0; i < 4; i++) {
            acc4[i].x *= al[i]; acc4[i].y *= al[i];
            acc4[i].z *= al[i]; acc4[i].w *= al[i];
        }
        for (int cb = 0; cb < 56; cb += 4) {
            float4 sv[4];
            #pragma unroll
            for (int i = 0; i < 4; i++)
                sv[i] = (rows[i] < 49)
                      ? *reinterpret_cast<const float4*>(&Sc[rows[i] * 56 + cb])
                      : make_float4(0.f, 0.f, 0.f, 0.f);
            #pragma unroll
            for (int cc = 0; cc < 4; cc++) {
                float4 vv = *reinterpret_cast<const float4*>(&Vs[(cb + cc) * 64 + d0]);
                #pragma unroll
                for (int i = 0; i < 4; i++) {
                    float s = (cc == 0) ? sv[i].x : (cc == 1) ? sv[i].y
                            : (cc == 2) ? sv[i].z : sv[i].w;
                    acc4[i].x = fmaf(s, vv.x, acc4[i].x);
                    acc4[i].y = fmaf(s, vv.y, acc4[i].y);
                    acc4[i].z = fmaf(s, vv.z, acc4[i].z);
                    acc4[i].w = fmaf(s, vv.w, acc4[i].w);
                }
            }
        }
        __syncthreads();
    }

    #pragma unroll
    for (int i = 0; i < 4; i++) {
        int r = rows[i];
        if (r >= 49) continue;
        float inv = 1.0f / lrow[r];
        int q = qg * 49 + r;
        float o[4] = {hswish(acc4[i].x * inv), hswish(acc4[i].y * inv),
                      hswish(acc4[i].z * inv), hswish(acc4[i].w * inv)};
        __nv_bfloat16 hh[4], ll[4];
        #pragma unroll
        for (int j = 0; j < 4; j++) {
            hh[j] = __float2bfloat16(o[j]);
            ll[j] = __float2bfloat16(o[j] - __bfloat162float(hh[j]));
        }
        size_t base = (size_t)(b * NQ + q) * DH + h * 64 + d0;
        reinterpret_cast<__nv_bfloat162*>(Yoh + base)[0] = __halves2bfloat162(hh[0], hh[1]);
        reinterpret_cast<__nv_bfloat162*>(Yoh + base)[1] = __halves2bfloat162(hh[2], hh[3]);
        reinterpret_cast<__nv_bfloat162*>(Yol + base)[0] = __halves2bfloat162(ll[0], ll[1]);
        reinterpret_cast<__nv_bfloat162*>(Yol + base)[1] = __halves2bfloat162(ll[2], ll[3]);
    }
}

// ---------------------------------------------------------------- final BN apply
__global__ void __launch_bounds__(256) bn_apply(
    const float* __restrict__ Y, const float* __restrict__ scale,
    const float* __restrict__ shift, float* __restrict__ out, int Ncols)
{
    const int idx = blockIdx.x * 256 + threadIdx.x;
    const int c = idx % Ncols;
    out[idx] = fmaf(Y[idx], scale[c], shift[c]);
}

// ---------------------------------------------------------------- launch
extern "C" void kernel_launch(void* const* d_in, const int* in_sizes, int n_in,
                              void* d_out, int out_size)
{
    const float* x    = (const float*)d_in[0];
    const float* W_kv = (const float*)d_in[1];
    const float* gkv  = (const float*)d_in[2];
    const float* bkv  = (const float*)d_in[3];
    const float* W_q  = (const float*)d_in[4];
    const float* gq   = (const float*)d_in[5];
    const float* bq   = (const float*)d_in[6];
    const float* W_p  = (const float*)d_in[7];
    const float* gp   = (const float*)d_in[8];
    const float* bp   = (const float*)d_in[9];
    const float* ab   = (const float*)d_in[10];
    const int*   bidx = (const int*)d_in[11];
    float* out = (float*)d_out;

    float *Ykv, *Yq, *Yp, *ps, *pq;
    float *sckv, *shkv, *scq, *shq, *scp, *shp;
    __nv_bfloat16 *xh, *xl, *Wkvh, *Wkvl, *Wqh, *Wql, *Wph, *Wpl, *Yoh, *Yol;
    cudaGetSymbolAddress((void**)&Ykv, g_Ykv);
    cudaGetSymbolAddress((void**)&Yq,  g_Yq);
    cudaGetSymbolAddress((void**)&Yp,  g_Yp);
    cudaGetSymbolAddress((void**)&ps,  g_ps);
    cudaGetSymbolAddress((void**)&pq,  g_pq);
    cudaGetSymbolAddress((void**)&sckv, g_sc_kv);
    cudaGetSymbolAddress((void**)&shkv, g_sh_kv);
    cudaGetSymbolAddress((void**)&scq,  g_sc_q);
    cudaGetSymbolAddress((void**)&shq,  g_sh_q);
    cudaGetSymbolAddress((void**)&scp,  g_sc_p);
    cudaGetSymbolAddress((void**)&shp,  g_sh_p);
    cudaGetSymbolAddress((void**)&xh,   g_xh);
    cudaGetSymbolAddress((void**)&xl,   g_xl);
    cudaGetSymbolAddress((void**)&Wkvh, g_Wkvh);
    cudaGetSymbolAddress((void**)&Wkvl, g_Wkvl);
    cudaGetSymbolAddress((void**)&Wqh,  g_Wqh);
    cudaGetSymbolAddress((void**)&Wql,  g_Wql);
    cudaGetSymbolAddress((void**)&Wph,  g_Wph);
    cudaGetSymbolAddress((void**)&Wpl,  g_Wpl);
    cudaGetSymbolAddress((void**)&Yoh,  g_Yoh);
    cudaGetSymbolAddress((void**)&Yol,  g_Yol);

    cudaFuncSetAttribute(gemm_mma<0>, cudaFuncAttributeMaxDynamicSharedMemorySize, GEMM_SMEM);
    cudaFuncSetAttribute(gemm_mma<1>, cudaFuncAttributeMaxDynamicSharedMemorySize, GEMM_SMEM);

    // 0) bf16 hi/lo splits
    cvt_split4<<<(unsigned)(((size_t)MKV * CC / 4 + 255) / 256), 256>>>(x, xh, xl, (size_t)MKV * CC / 4);
    cvt_split4<<<(unsigned)(((size_t)OKV * CC / 4 + 255) / 256), 256>>>(W_kv, Wkvh, Wkvl, (size_t)OKV * CC / 4);
    cvt_split4<<<(unsigned)(((size_t)OQ  * CC / 4 + 255) / 256), 256>>>(W_q, Wqh, Wql, (size_t)OQ * CC / 4);
    cvt_split4<<<(unsigned)(((size_t)OP  * DH / 4 + 255) / 256), 256>>>(W_p, Wph, Wpl, (size_t)OP * DH / 4);

    // 1) kv = x @ W_kv^T
    gemm_mma<0><<<dim3(OKV / 128, MKV / 128), 256, GEMM_SMEM>>>(xh, xl, Wkvh, Wkvl, Ykv, MKV, OKV, CC);
    col_partial<<<dim3(OKV / 256, 64), 256>>>(Ykv, ps, pq, MKV, OKV);
    bn_finalize<<<OKV / 256, 256>>>(ps, pq, gkv, bkv, sckv, shkv, OKV, 1.f / MKV);

    // 2) q = xq @ W_q^T (gathered rows)
    gemm_mma<1><<<dim3(OQ / 128, MQ / 128), 256, GEMM_SMEM>>>(xh, xl, Wqh, Wql, Yq, MQ, OQ, CC);
    col_partial<<<dim3(OQ / 256, 64), 256>>>(Yq, ps, pq, MQ, OQ);
    bn_finalize<<<OQ / 256, 256>>>(ps, pq, gq, bq, scq, shq, OQ, 1.f / MQ);

    // 3) attention + hard-swish (round-5 shape: 4 q-groups, 256 threads)
    attn_flash<<<dim3(4, HH, BB), 256>>>(
        Ykv, Yq, sckv, shkv, scq, shq, ab, bidx, Yoh, Yol);

    // 4) proj
    gemm_mma<0><<<dim3(OP / 128, MQ / 128), 256, GEMM_SMEM>>>(Yoh, Yol, Wph, Wpl, Yp, MQ, OP, DH);
    col_partial<<<dim3(OP / 256, 64), 256>>>(Yp, ps, pq, MQ, OP);
    bn_finalize<<<OP / 256, 256>>>(ps, pq, gp, bp, scp, shp, OP, 1.f / MQ);
    bn_apply<<<(MQ * OP) / 256, 256>>>(Yp, scp, shp, out, OP);
}